// round 16
// baseline (speedup 1.0000x reference)
#include <cuda_runtime.h>
#include <math.h>
#include <stdint.h>

#define BATCH 8
#define CIN   256
#define NPOS  1568
#define NH    4
#define DH    128
#define O3    1536
#define NT    25

// Scratch layouts:
//  pi(k) = ((k&3)<<2)|((k>>2)&3)           (16-groups; d-dim of Q/K, k-dim of W)
//  rho(j) = 4*((j>>1)&3) + 2*(j>>3) + (j&1) (tok-dim of V, 16-groups)
__device__ float g_q[BATCH*NH*NPOS*DH];   // [bh][tok][pi(d)], *scl*log2e, tf32
__device__ float g_k[BATCH*NH*NPOS*DH];   // [bh][tok][pi(d)], emb folded, tf32
__device__ float g_v[BATCH*NH*DH*NPOS];   // [bh][d][rho(tok)], tf32
__device__ float g_wh[O3*CIN];            // tf32(W), pi(k) layout
__device__ float g_wl[O3*CIN];            // tf32(W - tf32(W)), pi(k) layout

__device__ __forceinline__ float to_tf32(float x) {
    uint32_t u; asm("cvt.rna.tf32.f32 %0, %1;" : "=r"(u) : "f"(x));
    return __uint_as_float(u);
}
__device__ __forceinline__ float fast_exp2(float x) {
    float y; asm("ex2.approx.f32 %0, %1;" : "=f"(y) : "f"(x)); return y;
}
__device__ __forceinline__ void mma_tf32(float c[4],
        uint32_t a0, uint32_t a1, uint32_t a2, uint32_t a3,
        uint32_t b0, uint32_t b1) {
    asm volatile(
        "mma.sync.aligned.m16n8k8.row.col.f32.tf32.tf32.f32 "
        "{%0,%1,%2,%3}, {%4,%5,%6,%7}, {%8,%9}, {%0,%1,%2,%3};\n"
        : "+f"(c[0]), "+f"(c[1]), "+f"(c[2]), "+f"(c[3])
        : "r"(a0), "r"(a1), "r"(a2), "r"(a3), "r"(b0), "r"(b1));
}
__device__ __forceinline__ void cp16(uint32_t dst, const void* src, bool ok) {
    unsigned sz = ok ? 16u : 0u;
    asm volatile("cp.async.cg.shared.global [%0], [%1], 16, %2;\n"
                 :: "r"(dst), "l"(src), "r"(sz));
}
#define CP_COMMIT()  asm volatile("cp.async.commit_group;\n")
#define CP_WAIT(N)   asm volatile("cp.async.wait_group %0;\n" :: "n"(N))

// ---------------------------------------------------------------------------
// Kernel W: one-time hi/lo tf32 split of W_qkv, stored in pi(k) layout.
// ---------------------------------------------------------------------------
__global__ __launch_bounds__(256) void wsplit_kernel(const float* __restrict__ Wq)
{
    int idx = (blockIdx.x * 256 + threadIdx.x) * 4;
    float4 v = *(const float4*)&Wq[idx];
    float hx = to_tf32(v.x), hy = to_tf32(v.y), hz = to_tf32(v.z), hw = to_tf32(v.w);
    int p0 = (idx & ~15) | ((idx >> 2) & 3);
    g_wh[p0]    = hx;  g_wh[p0+4]  = hy;  g_wh[p0+8]  = hz;  g_wh[p0+12] = hw;
    g_wl[p0]    = to_tf32(v.x-hx);
    g_wl[p0+4]  = to_tf32(v.y-hy);
    g_wl[p0+8]  = to_tf32(v.z-hz);
    g_wl[p0+12] = to_tf32(v.w-hw);
}

// ---------------------------------------------------------------------------
// Kernel A: QKV projection via 3xTF32 compensated mma GEMM (round-14 version,
// unchanged).
// ---------------------------------------------------------------------------
__global__ __launch_bounds__(128) void qkv_kernel(
    const float* __restrict__ fmap,
    const float* __restrict__ pf, const float* __restrict__ ph,
    const float* __restrict__ pw)
{
    extern __shared__ float qsm[];
    float* Bh = qsm + 16384;
    float* Bl = qsm + 20480;
    float* Ts = qsm;

    const int tid  = threadIdx.x;
    const int lane = tid & 31, w = tid >> 5;
    const int gid  = lane >> 2, tig = lane & 3;
    const int row0 = w*16 + gid;
    const int pbase = blockIdx.x * 64;
    const int obase = blockIdx.y * 64;
    const int b     = blockIdx.z;
    const int vsw = (gid & 3) << 4;
    const int asw = tig << 3;
    const int r0 = tid >> 4, c4l = (tid & 15) * 4;
    const uint32_t sbase = (uint32_t)__cvta_generic_to_shared(qsm);

    float acc[8][4];
#pragma unroll
    for (int nb=0;nb<8;nb++)
#pragma unroll
        for (int c=0;c<4;c++) acc[nb][c] = 0.f;

    auto loadW = [&](int ks, int buf) {
        uint32_t dA = sbase + (uint32_t)buf * 32768u;
#pragma unroll
        for (int p=0;p<8;p++) {
            int r = r0 + p*8;
            uint32_t o = (uint32_t)(r*64 + (c4l ^ ((r&3)<<4))) * 4u;
            cp16(dA + o,          &g_wh[(obase + r)*CIN + ks*64 + c4l], true);
            cp16(dA + 16384u + o, &g_wl[(obase + r)*CIN + ks*64 + c4l], true);
        }
    };

    float4 rb[8];
    loadW(0, 0); CP_COMMIT();
#pragma unroll
    for (int p=0;p<8;p++) {
        int r = r0 + p*8;
        rb[p] = make_float4(0.f,0.f,0.f,0.f);
        if (pbase + c4l < NPOS)
            rb[p] = *(const float4*)&fmap[(size_t)(b*CIN + r)*NPOS + pbase + c4l];
    }

    for (int ks = 0; ks < 4; ks++) {
#pragma unroll
        for (int p=0;p<8;p++) {
            int r = r0 + p*8;
            float4 v = rb[p];
            float hx = to_tf32(v.x), hy = to_tf32(v.y), hz = to_tf32(v.z), hw = to_tf32(v.w);
            int o = r*64 + (c4l ^ ((r&3)<<3));
            *(float4*)&Bh[o] = make_float4(hx, hy, hz, hw);
            *(float4*)&Bl[o] = make_float4(to_tf32(v.x-hx), to_tf32(v.y-hy),
                                           to_tf32(v.z-hz), to_tf32(v.w-hw));
        }
        CP_WAIT(0);
        __syncthreads();

        if (ks < 3) {
            loadW(ks+1, (ks+1)&1); CP_COMMIT();
            int kn = (ks+1)*64;
#pragma unroll
            for (int p=0;p<8;p++) {
                int r = r0 + p*8;
                rb[p] = make_float4(0.f,0.f,0.f,0.f);
                if (pbase + c4l < NPOS)
                    rb[p] = *(const float4*)&fmap[(size_t)(b*CIN + kn + r)*NPOS + pbase + c4l];
            }
        }

        const float* Wh = qsm + (ks&1)*8192;
        const float* Wl = Wh + 4096;
#pragma unroll
        for (int kpi=0; kpi<4; kpi++) {
            int kb = kpi*16;
            uint32_t aeh0 = __float_as_uint(Bh[(kb+tig   )*64 + ( row0    ^ asw)]);
            uint32_t aeh1 = __float_as_uint(Bh[(kb+tig   )*64 + ((row0+8) ^ asw)]);
            uint32_t aeh2 = __float_as_uint(Bh[(kb+tig+4 )*64 + ( row0    ^ asw)]);
            uint32_t aeh3 = __float_as_uint(Bh[(kb+tig+4 )*64 + ((row0+8) ^ asw)]);
            uint32_t ael0 = __float_as_uint(Bl[(kb+tig   )*64 + ( row0    ^ asw)]);
            uint32_t ael1 = __float_as_uint(Bl[(kb+tig   )*64 + ((row0+8) ^ asw)]);
            uint32_t ael2 = __float_as_uint(Bl[(kb+tig+4 )*64 + ( row0    ^ asw)]);
            uint32_t ael3 = __float_as_uint(Bl[(kb+tig+4 )*64 + ((row0+8) ^ asw)]);
            uint32_t aoh0 = __float_as_uint(Bh[(kb+tig+8 )*64 + ( row0    ^ asw)]);
            uint32_t aoh1 = __float_as_uint(Bh[(kb+tig+8 )*64 + ((row0+8) ^ asw)]);
            uint32_t aoh2 = __float_as_uint(Bh[(kb+tig+12)*64 + ( row0    ^ asw)]);
            uint32_t aoh3 = __float_as_uint(Bh[(kb+tig+12)*64 + ((row0+8) ^ asw)]);
            uint32_t aol0 = __float_as_uint(Bl[(kb+tig+8 )*64 + ( row0    ^ asw)]);
            uint32_t aol1 = __float_as_uint(Bl[(kb+tig+8 )*64 + ((row0+8) ^ asw)]);
            uint32_t aol2 = __float_as_uint(Bl[(kb+tig+12)*64 + ( row0    ^ asw)]);
            uint32_t aol3 = __float_as_uint(Bl[(kb+tig+12)*64 + ((row0+8) ^ asw)]);
#pragma unroll
            for (int nb=0; nb<8; nb++) {
                int rr = nb*8 + gid;
                float4 wh4 = *(const float4*)&Wh[rr*64 + (kb ^ vsw) + tig*4];
                float4 wl4 = *(const float4*)&Wl[rr*64 + (kb ^ vsw) + tig*4];
                uint32_t whx=__float_as_uint(wh4.x), why=__float_as_uint(wh4.y);
                uint32_t whz=__float_as_uint(wh4.z), whw=__float_as_uint(wh4.w);
                uint32_t wlx=__float_as_uint(wl4.x), wly=__float_as_uint(wl4.y);
                uint32_t wlz=__float_as_uint(wl4.z), wlw=__float_as_uint(wl4.w);
                mma_tf32(acc[nb], aeh0,aeh1,aeh2,aeh3, wlx,wly);
                mma_tf32(acc[nb], ael0,ael1,ael2,ael3, whx,why);
                mma_tf32(acc[nb], aeh0,aeh1,aeh2,aeh3, whx,why);
                mma_tf32(acc[nb], aoh0,aoh1,aoh2,aoh3, wlz,wlw);
                mma_tf32(acc[nb], aol0,aol1,aol2,aol3, whz,whw);
                mma_tf32(acc[nb], aoh0,aoh1,aoh2,aoh3, whz,whw);
            }
        }
        __syncthreads();
    }

    const float scl = 0.08838834764831845f * 1.4426950408889634f;
    const int sec  = obase >> 9;
    const int head = (obase >> 7) & 3;
    const int d0   = obase & 127;
    const int bh   = b*NH + head;

    if (sec < 2) {
#pragma unroll
        for (int nb=0;nb<8;nb++)
#pragma unroll
            for (int half=0;half<2;half++)
#pragma unroll
                for (int e=0;e<2;e++)
                    Ts[(row0 + half*8)*65 + nb*8 + 2*tig + e] = acc[nb][half*2+e];
    } else {
#pragma unroll
        for (int nb=0;nb<8;nb++)
#pragma unroll
            for (int half=0;half<2;half++)
#pragma unroll
                for (int e=0;e<2;e++)
                    Ts[(nb*8 + 2*tig + e)*65 + row0 + half*8] = acc[nb][half*2+e];
    }
    __syncthreads();

    const int rr  = tid >> 4;
    const int c4  = (tid & 15) * 4;
    const int tq  = (c4 >> 2) & 3;
    const int cb  = c4 & ~15;
    const int lc0 = cb + tq, lc1 = cb + 4 + tq, lc2 = cb + 8 + tq, lc3 = cb + 12 + tq;
    const int lv0 = cb + 2*tq, lv1 = cb + 2*tq + 1, lv2 = cb + 2*tq + 8, lv3 = cb + 2*tq + 9;

#pragma unroll
    for (int pass=0; pass<8; pass++) {
        int r = rr + pass*8;
        if (sec == 2) {
            if (pbase + c4 < NPOS) {
                float v0 = Ts[r*65+lv0], v1 = Ts[r*65+lv1];
                float v2 = Ts[r*65+lv2], v3 = Ts[r*65+lv3];
                *(float4*)&g_v[((size_t)bh*DH + d0 + r)*NPOS + pbase + c4] =
                    make_float4(to_tf32(v0), to_tf32(v1), to_tf32(v2), to_tf32(v3));
            }
        } else {
            float v0 = Ts[r*65+lc0], v1 = Ts[r*65+lc1];
            float v2 = Ts[r*65+lc2], v3 = Ts[r*65+lc3];
            int pos = pbase + r;
            if (pos < NPOS) {
                size_t o_ = ((size_t)bh*NPOS + pos)*DH + d0 + c4;
                if (sec == 0) {
                    *(float4*)&g_q[o_] = make_float4(
                        to_tf32(v0*scl), to_tf32(v1*scl), to_tf32(v2*scl), to_tf32(v3*scl));
                } else {
                    int f_ = pos / 196; int rem = pos - f_*196;
                    int h_ = rem / 14;  int w_  = rem - h_*14;
                    const float* pfr = pf + f_*DH + d0;
                    const float* phr = ph + h_*DH + d0;
                    const float* pwr = pw + w_*DH + d0;
                    *(float4*)&g_k[o_] = make_float4(
                        to_tf32(v0 + pfr[lc0] + phr[lc0] + pwr[lc0]),
                        to_tf32(v1 + pfr[lc1] + phr[lc1] + pwr[lc1]),
                        to_tf32(v2 + pfr[lc2] + phr[lc2] + pwr[lc2]),
                        to_tf32(v3 + pfr[lc3] + phr[lc3] + pwr[lc3]));
                }
            }
        }
    }
}

// ---------------------------------------------------------------------------
// Kernel B: flash attention, Br=128/CTA (round-12 schedule, simplified):
// V double-buffered so K(t+1)+V(t+1) issue as ONE commit group right after
// the single loop-top sync; PV(t) runs same-iteration. 1 sync/tile (was 3).
// No S ping-pong, no extra registers. Math bit-identical to round-12/14.
// ---------------------------------------------------------------------------
__global__ __launch_bounds__(256, 1) void attn_kernel(float* __restrict__ out)
{
    extern __shared__ float sm[];
    float* Kb[2] = { sm, sm + 8192 };
    float* Vb[2] = { sm + 16384, sm + 24576 };   // [d=128][rho(tok)=64] each
    float* Od    = sm;                            // 128 x 132 overlay

    const int tid  = threadIdx.x;
    const int lane = tid & 31, w = tid >> 5;
    const int gid  = lane >> 2, tig = lane & 3;
    const int qt = blockIdx.x, bh = blockIdx.y;
    const int qbase = qt * 128;
    const int row0 = w*16 + gid;
    const int gsw = gid << 4;
    const int vsw = (gid & 3) << 4;

    const float* qp = g_q + (size_t)bh * NPOS * DH;
    const float* kp = g_k + (size_t)bh * NPOS * DH;
    const float* vp = g_v + (size_t)bh * DH * NPOS;

    // ---- Q staging through Kb[0], two 64-row passes ----
    uint32_t qa[16][4];
#pragma unroll
    for (int pass = 0; pass < 2; pass++) {
        int r0 = tid >> 5; int c4 = (tid & 31) * 4;
#pragma unroll
        for (int p=0;p<8;p++) {
            int r = r0 + p*8;
            float4 v = make_float4(0.f,0.f,0.f,0.f);
            int grow = qbase + pass*64 + r;
            if (grow < NPOS) v = *(const float4*)&qp[(size_t)grow*DH + c4];
            *(float4*)&Kb[0][r*128 + (c4 ^ ((r&7)<<4))] = v;
        }
        __syncthreads();
        if ((w >> 2) == pass) {
            int lr = row0 & 63;
#pragma unroll
            for (int kpi=0;kpi<8;kpi++) {
                float4 ra = *(const float4*)&Kb[0][ lr   *128 + ((kpi*16) ^ gsw) + tig*4];
                float4 rb = *(const float4*)&Kb[0][(lr+8)*128 + ((kpi*16) ^ gsw) + tig*4];
                qa[2*kpi  ][0] = __float_as_uint(ra.x); qa[2*kpi  ][1] = __float_as_uint(rb.x);
                qa[2*kpi  ][2] = __float_as_uint(ra.y); qa[2*kpi  ][3] = __float_as_uint(rb.y);
                qa[2*kpi+1][0] = __float_as_uint(ra.z); qa[2*kpi+1][1] = __float_as_uint(rb.z);
                qa[2*kpi+1][2] = __float_as_uint(ra.w); qa[2*kpi+1][3] = __float_as_uint(rb.w);
            }
        }
        __syncthreads();
    }

    const uint32_t smK0 = (uint32_t)__cvta_generic_to_shared(Kb[0]);
    const uint32_t smK1 = (uint32_t)__cvta_generic_to_shared(Kb[1]);
    const uint32_t smV0 = (uint32_t)__cvta_generic_to_shared(Vb[0]);
    const uint32_t smV1 = (uint32_t)__cvta_generic_to_shared(Vb[1]);
    const int lr0 = tid >> 5, lc4 = (tid & 31) * 4;
    const int vr0 = tid >> 4, vc4 = (tid & 15) * 4;

    // prologue: K(0)+V(0), ONE commit group
#pragma unroll
    for (int p=0;p<8;p++) {
        int r = lr0 + p*8;
        cp16(smK0 + (r*128 + (lc4 ^ ((r&7)<<4)))*4, &kp[(size_t)r*DH + lc4], r < NPOS);
    }
#pragma unroll
    for (int p=0;p<8;p++) {
        int r = vr0 + p*16;
        cp16(smV0 + (r*64 + (vc4 ^ ((r&3)<<4)))*4, &vp[(size_t)r*NPOS + vc4], vc4 < NPOS);
    }
    CP_COMMIT();

    float m0 = 0.f, m1 = 0.f;
    float l0 = 0.f, l1 = 0.f;
    float O[16][4];
#pragma unroll
    for (int nb=0;nb<16;nb++)
#pragma unroll
        for (int c=0;c<4;c++) O[nb][c] = 0.f;

    for (int t = 0; t < NT; t++) {
        const int kb = t * 64;
        const float* Ks = Kb[t & 1];
        const float* Vs = Vb[t & 1];
        CP_WAIT(0);             // K(t)+V(t) resident (group issued at t-1)
        __syncthreads();        // also: all reads of the other buffers are done

        // prefetch K(t+1)+V(t+1) as ONE group (into the other buffers; safe)
        if (t + 1 < NT) {
            int tn = t + 1;
            const float* kpn = kp + (size_t)tn*64*DH;
            const float* vpn = vp + (size_t)tn*64;
            uint32_t dstK = (tn & 1) ? smK1 : smK0;
            uint32_t dstV = (tn & 1) ? smV1 : smV0;
#pragma unroll
            for (int p=0;p<8;p++) {
                int r = lr0 + p*8;
                cp16(dstK + (r*128 + (lc4 ^ ((r&7)<<4)))*4,
                     &kpn[(size_t)r*DH + lc4], tn*64 + r < NPOS);
            }
#pragma unroll
            for (int p=0;p<8;p++) {
                int r = vr0 + p*16;
                cp16(dstV + (r*64 + (vc4 ^ ((r&3)<<4)))*4,
                     &vpn[(size_t)r*NPOS + vc4], tn*64 + vc4 < NPOS);
            }
            CP_COMMIT();
        }

        // ---- S = Q K'^T ----
        float S[8][4];
#pragma unroll
        for (int nb=0;nb<8;nb++)
#pragma unroll
            for (int c=0;c<4;c++) S[nb][c] = 0.f;
#pragma unroll
        for (int kpi=0;kpi<8;kpi++) {
#pragma unroll
            for (int nb=0;nb<8;nb++) {
                int rr = nb*8 + gid;
                float4 kv = *(const float4*)&Ks[rr*128 + ((kpi*16) ^ gsw) + tig*4];
                mma_tf32(S[nb], qa[2*kpi  ][0],qa[2*kpi  ][1],qa[2*kpi  ][2],qa[2*kpi  ][3],
                         __float_as_uint(kv.x), __float_as_uint(kv.y));
                mma_tf32(S[nb], qa[2*kpi+1][0],qa[2*kpi+1][1],qa[2*kpi+1][2],qa[2*kpi+1][3],
                         __float_as_uint(kv.z), __float_as_uint(kv.w));
            }
        }

        if (kb + 64 > NPOS) {
#pragma unroll
            for (int nb=0;nb<8;nb++) {
                int c0 = kb + nb*8 + 2*tig;
                if (c0     >= NPOS) { S[nb][0] = -1e30f; S[nb][2] = -1e30f; }
                if (c0 + 1 >= NPOS) { S[nb][1] = -1e30f; S[nb][3] = -1e30f; }
            }
        }

        if (t == 0) {
            float mx0 = -1e30f, mx1 = -1e30f;
#pragma unroll
            for (int nb=0;nb<8;nb++) {
                mx0 = fmaxf(mx0, fmaxf(S[nb][0], S[nb][1]));
                mx1 = fmaxf(mx1, fmaxf(S[nb][2], S[nb][3]));
            }
            mx0 = fmaxf(mx0, __shfl_xor_sync(0xffffffffu, mx0, 1));
            mx0 = fmaxf(mx0, __shfl_xor_sync(0xffffffffu, mx0, 2));
            mx1 = fmaxf(mx1, __shfl_xor_sync(0xffffffffu, mx1, 1));
            mx1 = fmaxf(mx1, __shfl_xor_sync(0xffffffffu, mx1, 2));
            m0 = mx0; m1 = mx1;
        }

        float rs0 = 0.f, rs1 = 0.f;
#pragma unroll
        for (int nb=0;nb<8;nb++) {
            S[nb][0] = fast_exp2(S[nb][0] - m0); rs0 += S[nb][0];
            S[nb][1] = fast_exp2(S[nb][1] - m0); rs0 += S[nb][1];
            S[nb][2] = fast_exp2(S[nb][2] - m1); rs1 += S[nb][2];
            S[nb][3] = fast_exp2(S[nb][3] - m1); rs1 += S[nb][3];
        }
        l0 += rs0;
        l1 += rs1;

        // ---- O += P V(t) : V already resident; S c-frags ARE the A-frags ----
#pragma unroll
        for (int kpi=0;kpi<4;kpi++) {
            int e = 2*kpi, o = 2*kpi+1;
            uint32_t ea0 = __float_as_uint(to_tf32(S[e][0]));
            uint32_t ea1 = __float_as_uint(to_tf32(S[e][2]));
            uint32_t ea2 = __float_as_uint(to_tf32(S[e][1]));
            uint32_t ea3 = __float_as_uint(to_tf32(S[e][3]));
            uint32_t oa0 = __float_as_uint(to_tf32(S[o][0]));
            uint32_t oa1 = __float_as_uint(to_tf32(S[o][2]));
            uint32_t oa2 = __float_as_uint(to_tf32(S[o][1]));
            uint32_t oa3 = __float_as_uint(to_tf32(S[o][3]));
#pragma unroll
            for (int nb=0;nb<16;nb++) {
                int rr = nb*8 + gid;
                float4 vv = *(const float4*)&Vs[rr*64 + ((kpi*16) ^ vsw) + tig*4];
                mma_tf32(O[nb], ea0,ea1,ea2,ea3,
                         __float_as_uint(vv.x), __float_as_uint(vv.y));
                mma_tf32(O[nb], oa0,oa1,oa2,oa3,
                         __float_as_uint(vv.z), __float_as_uint(vv.w));
            }
        }
        // no post-PV sync: next loop-top sync covers buffer reuse
    }

    l0 += __shfl_xor_sync(0xffffffffu, l0, 1);
    l0 += __shfl_xor_sync(0xffffffffu, l0, 2);
    l1 += __shfl_xor_sync(0xffffffffu, l1, 1);
    l1 += __shfl_xor_sync(0xffffffffu, l1, 2);

    __syncthreads();            // all PV reads done before Od overlay
    float inv0 = 1.0f / l0, inv1 = 1.0f / l1;
#pragma unroll
    for (int nb=0;nb<16;nb++) {
        Od[(nb*8 + 2*tig    )*132 + row0    ] = O[nb][0] * inv0;
        Od[(nb*8 + 2*tig + 1)*132 + row0    ] = O[nb][1] * inv0;
        Od[(nb*8 + 2*tig    )*132 + row0 + 8] = O[nb][2] * inv1;
        Od[(nb*8 + 2*tig + 1)*132 + row0 + 8] = O[nb][3] * inv1;
    }
    __syncthreads();

    const int b = bh >> 2, head = bh & 3;
    const size_t ch0 = (size_t)b*512 + head*128;
    {
        int t2 = (tid & 63) * 2;
#pragma unroll
        for (int p=0;p<32;p++) {
            int dd = (tid >> 6) + p*4;
            if (qbase + t2 < NPOS) {
                float2 v = *(const float2*)&Od[dd*132 + t2];
                *(float2*)&out[(ch0 + dd)*NPOS + qbase + t2] = v;
            }
        }
    }
}

// ---------------------------------------------------------------------------
extern "C" void kernel_launch(void* const* d_in, const int* in_sizes, int n_in,
                              void* d_out, int out_size)
{
    const float* fmap = (const float*)d_in[0];
    const float* Wq   = (const float*)d_in[1];
    const float* pf   = (const float*)d_in[2];
    const float* ph   = (const float*)d_in[3];
    const float* pw   = (const float*)d_in[4];
    float* out = (float*)d_out;

    wsplit_kernel<<<O3*CIN/1024, 256>>>(Wq);

    const size_t smemA = (size_t)24576 * sizeof(float);   // 96 KB
    cudaFuncSetAttribute(qkv_kernel, cudaFuncAttributeMaxDynamicSharedMemorySize,
                         (int)smemA);
    dim3 gA(25, 24, BATCH);
    qkv_kernel<<<gA, 128, smemA>>>(fmap, pf, ph, pw);

    const size_t smemB = (size_t)32768 * sizeof(float);   // 128 KB
    cudaFuncSetAttribute(attn_kernel, cudaFuncAttributeMaxDynamicSharedMemorySize,
                         (int)smemB);
    dim3 gB(13, 32);
    attn_kernel<<<gB, 256, smemB>>>(out);
}

// round 17
// speedup vs baseline: 1.0892x; 1.0892x over previous
#include <cuda_runtime.h>
#include <math.h>
#include <stdint.h>

#define BATCH 8
#define CIN   256
#define NPOS  1568
#define NH    4
#define DH    128
#define O3    1536

// Scratch layouts:
//  pi(k) = ((k&3)<<2)|((k>>2)&3)           (16-groups; d-dim of Q/K, k-dim of W)
//  rho(j) = 4*((j>>1)&3) + 2*(j>>3) + (j&1) (tok-dim of V, 16-groups)
__device__ float g_q[BATCH*NH*NPOS*DH];   // [bh][tok][pi(d)], *scl*log2e, tf32
__device__ float g_k[BATCH*NH*NPOS*DH];   // [bh][tok][pi(d)], emb folded, tf32
__device__ float g_v[BATCH*NH*DH*NPOS];   // [bh][d][rho(tok)], tf32
__device__ float g_wh[O3*CIN];            // tf32(W), pi(k) layout
__device__ float g_wl[O3*CIN];            // tf32(W - tf32(W)), pi(k) layout

__device__ __forceinline__ float to_tf32(float x) {
    uint32_t u; asm("cvt.rna.tf32.f32 %0, %1;" : "=r"(u) : "f"(x));
    return __uint_as_float(u);
}
__device__ __forceinline__ float fast_exp2(float x) {
    float y; asm("ex2.approx.f32 %0, %1;" : "=f"(y) : "f"(x)); return y;
}
__device__ __forceinline__ void mma_tf32(float c[4],
        uint32_t a0, uint32_t a1, uint32_t a2, uint32_t a3,
        uint32_t b0, uint32_t b1) {
    asm volatile(
        "mma.sync.aligned.m16n8k8.row.col.f32.tf32.tf32.f32 "
        "{%0,%1,%2,%3}, {%4,%5,%6,%7}, {%8,%9}, {%0,%1,%2,%3};\n"
        : "+f"(c[0]), "+f"(c[1]), "+f"(c[2]), "+f"(c[3])
        : "r"(a0), "r"(a1), "r"(a2), "r"(a3), "r"(b0), "r"(b1));
}
__device__ __forceinline__ void cp16(uint32_t dst, const void* src, bool ok) {
    unsigned sz = ok ? 16u : 0u;
    asm volatile("cp.async.cg.shared.global [%0], [%1], 16, %2;\n"
                 :: "r"(dst), "l"(src), "r"(sz));
}
#define CP_COMMIT()  asm volatile("cp.async.commit_group;\n")
#define CP_WAIT(N)   asm volatile("cp.async.wait_group %0;\n" :: "n"(N))

// ---------------------------------------------------------------------------
// Kernel W: one-time hi/lo tf32 split of W_qkv, stored in pi(k) layout.
// ---------------------------------------------------------------------------
__global__ __launch_bounds__(256) void wsplit_kernel(const float* __restrict__ Wq)
{
    int idx = (blockIdx.x * 256 + threadIdx.x) * 4;
    float4 v = *(const float4*)&Wq[idx];
    float hx = to_tf32(v.x), hy = to_tf32(v.y), hz = to_tf32(v.z), hw = to_tf32(v.w);
    int p0 = (idx & ~15) | ((idx >> 2) & 3);
    g_wh[p0]    = hx;  g_wh[p0+4]  = hy;  g_wh[p0+8]  = hz;  g_wh[p0+12] = hw;
    g_wl[p0]    = to_tf32(v.x-hx);
    g_wl[p0+4]  = to_tf32(v.y-hy);
    g_wl[p0+8]  = to_tf32(v.z-hz);
    g_wl[p0+12] = to_tf32(v.w-hw);
}

// ---------------------------------------------------------------------------
// Kernel A: QKV projection via 3xTF32 compensated mma GEMM.
// fmap now stored RAW in smem (half the STS); hi/lo split computed in
// registers at A-fragment load time (half the A-side LDS; same bits).
// ---------------------------------------------------------------------------
__global__ __launch_bounds__(128) void qkv_kernel(
    const float* __restrict__ fmap,
    const float* __restrict__ pf, const float* __restrict__ ph,
    const float* __restrict__ pw)
{
    extern __shared__ float qsm[];
    // [Wh0 0][Wl0 4096][Wh1 8192][Wl1 12288][Bs 16384..20479]
    float* Bs = qsm + 16384;   // fmap raw: [k][pos ^ ((k&3)<<3)]
    float* Ts = qsm;           // 64x65 epilogue overlay

    const int tid  = threadIdx.x;
    const int lane = tid & 31, w = tid >> 5;
    const int gid  = lane >> 2, tig = lane & 3;
    const int row0 = w*16 + gid;            // pos-row within tile (m-dim)
    const int pbase = blockIdx.x * 64;
    const int obase = blockIdx.y * 64;
    const int b     = blockIdx.z;
    const int vsw = (gid & 3) << 4;         // W-tile swizzle key
    const int asw = tig << 3;               // fmap A-frag swizzle key
    const int r0 = tid >> 4, c4l = (tid & 15) * 4;
    const uint32_t sbase = (uint32_t)__cvta_generic_to_shared(qsm);

    float acc[8][4];
#pragma unroll
    for (int nb=0;nb<8;nb++)
#pragma unroll
        for (int c=0;c<4;c++) acc[nb][c] = 0.f;

    auto loadW = [&](int ks, int buf) {
        uint32_t dA = sbase + (uint32_t)buf * 32768u;
#pragma unroll
        for (int p=0;p<8;p++) {
            int r = r0 + p*8;
            uint32_t o = (uint32_t)(r*64 + (c4l ^ ((r&3)<<4))) * 4u;
            cp16(dA + o,          &g_wh[(obase + r)*CIN + ks*64 + c4l], true);
            cp16(dA + 16384u + o, &g_wl[(obase + r)*CIN + ks*64 + c4l], true);
        }
    };

    float4 rb[8];
    loadW(0, 0); CP_COMMIT();
#pragma unroll
    for (int p=0;p<8;p++) {
        int r = r0 + p*8;
        rb[p] = make_float4(0.f,0.f,0.f,0.f);
        if (pbase + c4l < NPOS)
            rb[p] = *(const float4*)&fmap[(size_t)(b*CIN + r)*NPOS + pbase + c4l];
    }

    for (int ks = 0; ks < 4; ks++) {
        // store fmap B(ks) RAW: [k][pos] with ((k&3)<<3) swizzle
#pragma unroll
        for (int p=0;p<8;p++) {
            int r = r0 + p*8;
            *(float4*)&Bs[r*64 + (c4l ^ ((r&3)<<3))] = rb[p];
        }
        CP_WAIT(0);            // W(ks) resident
        __syncthreads();

        if (ks < 3) {
            loadW(ks+1, (ks+1)&1); CP_COMMIT();
            int kn = (ks+1)*64;
#pragma unroll
            for (int p=0;p<8;p++) {
                int r = r0 + p*8;
                rb[p] = make_float4(0.f,0.f,0.f,0.f);
                if (pbase + c4l < NPOS)
                    rb[p] = *(const float4*)&fmap[(size_t)(b*CIN + kn + r)*NPOS + pbase + c4l];
            }
        }

        const float* Wh = qsm + (ks&1)*8192;
        const float* Wl = Wh + 4096;
#pragma unroll
        for (int kpi=0; kpi<4; kpi++) {
            int kb = kpi*16;
            // raw fmap A values (8 scalars), split hi/lo in registers
            float re0 = Bs[(kb+tig   )*64 + ( row0    ^ asw)];
            float re1 = Bs[(kb+tig   )*64 + ((row0+8) ^ asw)];
            float re2 = Bs[(kb+tig+4 )*64 + ( row0    ^ asw)];
            float re3 = Bs[(kb+tig+4 )*64 + ((row0+8) ^ asw)];
            float ro0 = Bs[(kb+tig+8 )*64 + ( row0    ^ asw)];
            float ro1 = Bs[(kb+tig+8 )*64 + ((row0+8) ^ asw)];
            float ro2 = Bs[(kb+tig+12)*64 + ( row0    ^ asw)];
            float ro3 = Bs[(kb+tig+12)*64 + ((row0+8) ^ asw)];
            float feh0 = to_tf32(re0), feh1 = to_tf32(re1);
            float feh2 = to_tf32(re2), feh3 = to_tf32(re3);
            float foh0 = to_tf32(ro0), foh1 = to_tf32(ro1);
            float foh2 = to_tf32(ro2), foh3 = to_tf32(ro3);
            uint32_t aeh0 = __float_as_uint(feh0), aeh1 = __float_as_uint(feh1);
            uint32_t aeh2 = __float_as_uint(feh2), aeh3 = __float_as_uint(feh3);
            uint32_t aoh0 = __float_as_uint(foh0), aoh1 = __float_as_uint(foh1);
            uint32_t aoh2 = __float_as_uint(foh2), aoh3 = __float_as_uint(foh3);
            uint32_t ael0 = __float_as_uint(to_tf32(re0 - feh0));
            uint32_t ael1 = __float_as_uint(to_tf32(re1 - feh1));
            uint32_t ael2 = __float_as_uint(to_tf32(re2 - feh2));
            uint32_t ael3 = __float_as_uint(to_tf32(re3 - feh3));
            uint32_t aol0 = __float_as_uint(to_tf32(ro0 - foh0));
            uint32_t aol1 = __float_as_uint(to_tf32(ro1 - foh1));
            uint32_t aol2 = __float_as_uint(to_tf32(ro2 - foh2));
            uint32_t aol3 = __float_as_uint(to_tf32(ro3 - foh3));
#pragma unroll
            for (int nb=0; nb<8; nb++) {
                int rr = nb*8 + gid;
                float4 wh4 = *(const float4*)&Wh[rr*64 + (kb ^ vsw) + tig*4];
                float4 wl4 = *(const float4*)&Wl[rr*64 + (kb ^ vsw) + tig*4];
                uint32_t whx=__float_as_uint(wh4.x), why=__float_as_uint(wh4.y);
                uint32_t whz=__float_as_uint(wh4.z), whw=__float_as_uint(wh4.w);
                uint32_t wlx=__float_as_uint(wl4.x), wly=__float_as_uint(wl4.y);
                uint32_t wlz=__float_as_uint(wl4.z), wlw=__float_as_uint(wl4.w);
                mma_tf32(acc[nb], aeh0,aeh1,aeh2,aeh3, wlx,wly);
                mma_tf32(acc[nb], ael0,ael1,ael2,ael3, whx,why);
                mma_tf32(acc[nb], aeh0,aeh1,aeh2,aeh3, whx,why);
                mma_tf32(acc[nb], aoh0,aoh1,aoh2,aoh3, wlz,wlw);
                mma_tf32(acc[nb], aol0,aol1,aol2,aol3, whz,whw);
                mma_tf32(acc[nb], aoh0,aoh1,aoh2,aoh3, whz,whw);
            }
        }
        __syncthreads();
    }

    const float scl = 0.08838834764831845f * 1.4426950408889634f;
    const int sec  = obase >> 9;
    const int head = (obase >> 7) & 3;
    const int d0   = obase & 127;
    const int bh   = b*NH + head;

    // c-frag: rows = pos (row0 + half*8), cols = o (nb*8 + 2*tig + e)
    if (sec < 2) {
#pragma unroll
        for (int nb=0;nb<8;nb++)
#pragma unroll
            for (int half=0;half<2;half++)
#pragma unroll
                for (int e=0;e<2;e++)
                    Ts[(row0 + half*8)*65 + nb*8 + 2*tig + e] = acc[nb][half*2+e];
    } else {
#pragma unroll
        for (int nb=0;nb<8;nb++)
#pragma unroll
            for (int half=0;half<2;half++)
#pragma unroll
                for (int e=0;e<2;e++)
                    Ts[(nb*8 + 2*tig + e)*65 + row0 + half*8] = acc[nb][half*2+e];
    }
    __syncthreads();

    const int rr  = tid >> 4;
    const int c4  = (tid & 15) * 4;
    const int tq  = (c4 >> 2) & 3;
    const int cb  = c4 & ~15;
    const int lc0 = cb + tq, lc1 = cb + 4 + tq, lc2 = cb + 8 + tq, lc3 = cb + 12 + tq;
    const int lv0 = cb + 2*tq, lv1 = cb + 2*tq + 1, lv2 = cb + 2*tq + 8, lv3 = cb + 2*tq + 9;

#pragma unroll
    for (int pass=0; pass<8; pass++) {
        int r = rr + pass*8;
        if (sec == 2) {
            if (pbase + c4 < NPOS) {
                float v0 = Ts[r*65+lv0], v1 = Ts[r*65+lv1];
                float v2 = Ts[r*65+lv2], v3 = Ts[r*65+lv3];
                *(float4*)&g_v[((size_t)bh*DH + d0 + r)*NPOS + pbase + c4] =
                    make_float4(to_tf32(v0), to_tf32(v1), to_tf32(v2), to_tf32(v3));
            }
        } else {
            float v0 = Ts[r*65+lc0], v1 = Ts[r*65+lc1];
            float v2 = Ts[r*65+lc2], v3 = Ts[r*65+lc3];
            int pos = pbase + r;
            if (pos < NPOS) {
                size_t o_ = ((size_t)bh*NPOS + pos)*DH + d0 + c4;
                if (sec == 0) {
                    *(float4*)&g_q[o_] = make_float4(
                        to_tf32(v0*scl), to_tf32(v1*scl), to_tf32(v2*scl), to_tf32(v3*scl));
                } else {
                    int f_ = pos / 196; int rem = pos - f_*196;
                    int h_ = rem / 14;  int w_  = rem - h_*14;
                    const float* pfr = pf + f_*DH + d0;
                    const float* phr = ph + h_*DH + d0;
                    const float* pwr = pw + w_*DH + d0;
                    *(float4*)&g_k[o_] = make_float4(
                        to_tf32(v0 + pfr[lc0] + phr[lc0] + pwr[lc0]),
                        to_tf32(v1 + pfr[lc1] + phr[lc1] + pwr[lc1]),
                        to_tf32(v2 + pfr[lc2] + phr[lc2] + pwr[lc2]),
                        to_tf32(v3 + pfr[lc3] + phr[lc3] + pwr[lc3]));
                }
            }
        }
    }
}

// ---------------------------------------------------------------------------
// Kernel B: flash attention (round-12/14 version verbatim — best measured).
// Br=128/CTA, 256 threads; fixed-reference-max softmax; S c-frags feed PV
// directly (sigma/rho layout); cp.async double-buffered K + pipelined V.
// ---------------------------------------------------------------------------
__global__ __launch_bounds__(256, 1) void attn_kernel(float* __restrict__ out)
{
    extern __shared__ float sm[];
    float* Kb[2] = { sm, sm + 8192 };
    float* Vb    = sm + 16384;         // [d=128][rho(tok)=64]
    float* Od    = sm;                 // 128 x 132 overlay

    const int tid  = threadIdx.x;
    const int lane = tid & 31, w = tid >> 5;
    const int gid  = lane >> 2, tig = lane & 3;
    const int qt = blockIdx.x, bh = blockIdx.y;
    const int qbase = qt * 128;
    const int row0 = w*16 + gid;
    const int gsw = gid << 4;
    const int vsw = (gid & 3) << 4;

    const float* qp = g_q + (size_t)bh * NPOS * DH;
    const float* kp = g_k + (size_t)bh * NPOS * DH;
    const float* vp = g_v + (size_t)bh * DH * NPOS;

    // ---- Q staging through Kb[0], two 64-row passes ----
    uint32_t qa[16][4];
#pragma unroll
    for (int pass = 0; pass < 2; pass++) {
        int r0 = tid >> 5; int c4 = (tid & 31) * 4;
#pragma unroll
        for (int p=0;p<8;p++) {
            int r = r0 + p*8;
            float4 v = make_float4(0.f,0.f,0.f,0.f);
            int grow = qbase + pass*64 + r;
            if (grow < NPOS) v = *(const float4*)&qp[(size_t)grow*DH + c4];
            *(float4*)&Kb[0][r*128 + (c4 ^ ((r&7)<<4))] = v;
        }
        __syncthreads();
        if ((w >> 2) == pass) {
            int lr = row0 & 63;
#pragma unroll
            for (int kpi=0;kpi<8;kpi++) {
                float4 ra = *(const float4*)&Kb[0][ lr   *128 + ((kpi*16) ^ gsw) + tig*4];
                float4 rb = *(const float4*)&Kb[0][(lr+8)*128 + ((kpi*16) ^ gsw) + tig*4];
                qa[2*kpi  ][0] = __float_as_uint(ra.x); qa[2*kpi  ][1] = __float_as_uint(rb.x);
                qa[2*kpi  ][2] = __float_as_uint(ra.y); qa[2*kpi  ][3] = __float_as_uint(rb.y);
                qa[2*kpi+1][0] = __float_as_uint(ra.z); qa[2*kpi+1][1] = __float_as_uint(rb.z);
                qa[2*kpi+1][2] = __float_as_uint(ra.w); qa[2*kpi+1][3] = __float_as_uint(rb.w);
            }
        }
        __syncthreads();
    }

    const uint32_t smK0 = (uint32_t)__cvta_generic_to_shared(Kb[0]);
    const uint32_t smK1 = (uint32_t)__cvta_generic_to_shared(Kb[1]);
    const uint32_t smV  = (uint32_t)__cvta_generic_to_shared(Vb);
    const int lr0 = tid >> 5, lc4 = (tid & 31) * 4;
    const int vr0 = tid >> 4, vc4 = (tid & 15) * 4;

#pragma unroll
    for (int p=0;p<8;p++) {
        int r = lr0 + p*8;
        cp16(smK0 + (r*128 + (lc4 ^ ((r&7)<<4)))*4, &kp[(size_t)r*DH + lc4], r < NPOS);
    }
    CP_COMMIT();
#pragma unroll
    for (int p=0;p<8;p++) {
        int r = vr0 + p*16;
        cp16(smV + (r*64 + (vc4 ^ ((r&3)<<4)))*4, &vp[(size_t)r*NPOS + vc4], vc4 < NPOS);
    }
    CP_COMMIT();

    float m0 = 0.f, m1 = 0.f;
    float l0 = 0.f, l1 = 0.f;
    float O[16][4];
#pragma unroll
    for (int nb=0;nb<16;nb++)
#pragma unroll
        for (int c=0;c<4;c++) O[nb][c] = 0.f;

    for (int t = 0; t < 25; t++) {
        const int kb = t * 64;
        const float* Ks = Kb[t & 1];
        CP_WAIT(1);
        __syncthreads();

        float S[8][4];
#pragma unroll
        for (int nb=0;nb<8;nb++)
#pragma unroll
            for (int c=0;c<4;c++) S[nb][c] = 0.f;
#pragma unroll
        for (int kpi=0;kpi<8;kpi++) {
#pragma unroll
            for (int nb=0;nb<8;nb++) {
                int rr = nb*8 + gid;
                float4 kv = *(const float4*)&Ks[rr*128 + ((kpi*16) ^ gsw) + tig*4];
                mma_tf32(S[nb], qa[2*kpi  ][0],qa[2*kpi  ][1],qa[2*kpi  ][2],qa[2*kpi  ][3],
                         __float_as_uint(kv.x), __float_as_uint(kv.y));
                mma_tf32(S[nb], qa[2*kpi+1][0],qa[2*kpi+1][1],qa[2*kpi+1][2],qa[2*kpi+1][3],
                         __float_as_uint(kv.z), __float_as_uint(kv.w));
            }
        }

        {   // prefetch K(t+1)
            int tn = (t+1 < 25) ? t+1 : 24;
            const float* kpn = kp + (size_t)tn*64*DH;
            uint32_t dstK = (t & 1) ? smK0 : smK1;
#pragma unroll
            for (int p=0;p<8;p++) {
                int r = lr0 + p*8;
                cp16(dstK + (r*128 + (lc4 ^ ((r&7)<<4)))*4,
                     &kpn[(size_t)r*DH + lc4], tn*64 + r < NPOS);
            }
            CP_COMMIT();
        }

        if (kb + 64 > NPOS) {
#pragma unroll
            for (int nb=0;nb<8;nb++) {
                int c0 = kb + nb*8 + 2*tig;
                if (c0     >= NPOS) { S[nb][0] = -1e30f; S[nb][2] = -1e30f; }
                if (c0 + 1 >= NPOS) { S[nb][1] = -1e30f; S[nb][3] = -1e30f; }
            }
        }

        if (t == 0) {
            float mx0 = -1e30f, mx1 = -1e30f;
#pragma unroll
            for (int nb=0;nb<8;nb++) {
                mx0 = fmaxf(mx0, fmaxf(S[nb][0], S[nb][1]));
                mx1 = fmaxf(mx1, fmaxf(S[nb][2], S[nb][3]));
            }
            mx0 = fmaxf(mx0, __shfl_xor_sync(0xffffffffu, mx0, 1));
            mx0 = fmaxf(mx0, __shfl_xor_sync(0xffffffffu, mx0, 2));
            mx1 = fmaxf(mx1, __shfl_xor_sync(0xffffffffu, mx1, 1));
            mx1 = fmaxf(mx1, __shfl_xor_sync(0xffffffffu, mx1, 2));
            m0 = mx0; m1 = mx1;
        }

        float rs0 = 0.f, rs1 = 0.f;
#pragma unroll
        for (int nb=0;nb<8;nb++) {
            S[nb][0] = fast_exp2(S[nb][0] - m0); rs0 += S[nb][0];
            S[nb][1] = fast_exp2(S[nb][1] - m0); rs0 += S[nb][1];
            S[nb][2] = fast_exp2(S[nb][2] - m1); rs1 += S[nb][2];
            S[nb][3] = fast_exp2(S[nb][3] - m1); rs1 += S[nb][3];
        }
        l0 += rs0;
        l1 += rs1;

        CP_WAIT(1);
        __syncthreads();

        // ---- O += P V : S c-frags ARE the A-frags (sigma/rho layout) ----
#pragma unroll
        for (int kpi=0;kpi<4;kpi++) {
            int e = 2*kpi, o = 2*kpi+1;
            uint32_t ea0 = __float_as_uint(to_tf32(S[e][0]));
            uint32_t ea1 = __float_as_uint(to_tf32(S[e][2]));
            uint32_t ea2 = __float_as_uint(to_tf32(S[e][1]));
            uint32_t ea3 = __float_as_uint(to_tf32(S[e][3]));
            uint32_t oa0 = __float_as_uint(to_tf32(S[o][0]));
            uint32_t oa1 = __float_as_uint(to_tf32(S[o][2]));
            uint32_t oa2 = __float_as_uint(to_tf32(S[o][1]));
            uint32_t oa3 = __float_as_uint(to_tf32(S[o][3]));
#pragma unroll
            for (int nb=0;nb<16;nb++) {
                int rr = nb*8 + gid;
                float4 vv = *(const float4*)&Vb[rr*64 + ((kpi*16) ^ vsw) + tig*4];
                mma_tf32(O[nb], ea0,ea1,ea2,ea3,
                         __float_as_uint(vv.x), __float_as_uint(vv.y));
                mma_tf32(O[nb], oa0,oa1,oa2,oa3,
                         __float_as_uint(vv.z), __float_as_uint(vv.w));
            }
        }
        __syncthreads();

        {   // prefetch V(t+1)
            int tn = (t+1 < 25) ? t+1 : 24;
            const float* vpn = vp + (size_t)tn*64;
#pragma unroll
            for (int p=0;p<8;p++) {
                int r = vr0 + p*16;
                cp16(smV + (r*64 + (vc4 ^ ((r&3)<<4)))*4,
                     &vpn[(size_t)r*NPOS + vc4], tn*64 + vc4 < NPOS);
            }
            CP_COMMIT();
        }
    }

    l0 += __shfl_xor_sync(0xffffffffu, l0, 1);
    l0 += __shfl_xor_sync(0xffffffffu, l0, 2);
    l1 += __shfl_xor_sync(0xffffffffu, l1, 1);
    l1 += __shfl_xor_sync(0xffffffffu, l1, 2);

    CP_WAIT(0);
    __syncthreads();
    float inv0 = 1.0f / l0, inv1 = 1.0f / l1;
#pragma unroll
    for (int nb=0;nb<16;nb++) {
        Od[(nb*8 + 2*tig    )*132 + row0    ] = O[nb][0] * inv0;
        Od[(nb*8 + 2*tig + 1)*132 + row0    ] = O[nb][1] * inv0;
        Od[(nb*8 + 2*tig    )*132 + row0 + 8] = O[nb][2] * inv1;
        Od[(nb*8 + 2*tig + 1)*132 + row0 + 8] = O[nb][3] * inv1;
    }
    __syncthreads();

    const int b = bh >> 2, head = bh & 3;
    const size_t ch0 = (size_t)b*512 + head*128;
    {
        int t2 = (tid & 63) * 2;
#pragma unroll
        for (int p=0;p<32;p++) {
            int dd = (tid >> 6) + p*4;
            if (qbase + t2 < NPOS) {
                float2 v = *(const float2*)&Od[dd*132 + t2];
                *(float2*)&out[(ch0 + dd)*NPOS + qbase + t2] = v;
            }
        }
    }
}

// ---------------------------------------------------------------------------
extern "C" void kernel_launch(void* const* d_in, const int* in_sizes, int n_in,
                              void* d_out, int out_size)
{
    const float* fmap = (const float*)d_in[0];
    const float* Wq   = (const float*)d_in[1];
    const float* pf   = (const float*)d_in[2];
    const float* ph   = (const float*)d_in[3];
    const float* pw   = (const float*)d_in[4];
    float* out = (float*)d_out;

    wsplit_kernel<<<O3*CIN/1024, 256>>>(Wq);

    const size_t smemA = (size_t)20480 * sizeof(float);   // 80 KB
    cudaFuncSetAttribute(qkv_kernel, cudaFuncAttributeMaxDynamicSharedMemorySize,
                         (int)smemA);
    dim3 gA(25, 24, BATCH);
    qkv_kernel<<<gA, 128, smemA>>>(fmap, pf, ph, pw);

    const size_t smemB = (size_t)24576 * sizeof(float);   // 96 KB
    cudaFuncSetAttribute(attn_kernel, cudaFuncAttributeMaxDynamicSharedMemorySize,
                         (int)smemB);
    dim3 gB(13, 32);
    attn_kernel<<<gB, 256, smemB>>>(out);
}